// round 11
// baseline (speedup 1.0000x reference)
#include <cuda_runtime.h>
#include <cstdint>
#include <cstddef>

#define BATCH    64
#define SEQ      2048
#define INPUT    8
#define HIDDEN   512
#define NUM_SEEDS 4
#define DD       12
#define OUTK     10
#define ALPHA_F  0.1f
#define K1_F     (0.1f * (500.0f/512.0f))
#define QSCALE   131072.0f           /* 2^17 fixed-point scale (magic-round safe) */
#define QINV     (1.0f/131072.0f)
#define MAGIC_F  12582912.0f         /* 1.5 * 2^23 */
#define MAGIC_I  0x4B400000

// ---------------- scratch (static __device__ — no allocation) ----------------
__device__ float g_m0[NUM_SEEDS][HIDDEN];
__device__ float g_m1[NUM_SEEDS][HIDDEN];
__device__ float g_n0[NUM_SEEDS][HIDDEN];
__device__ float g_n1[NUM_SEEDS][HIDDEN];
__device__ float g_I [NUM_SEEDS][HIDDEN][INPUT];

// native tanh (MUFU.TANH): 1 MUFU op, ~16cyc; rel err ~2^-11.
__device__ __forceinline__ float fast_tanh(float x) {
    float r;
    asm("tanh.approx.f32 %0, %1;" : "=f"(r) : "f"(x));
    return r;
}

// ---- packed f32x2 helpers (Blackwell FFMA2 via PTX) ----
__device__ __forceinline__ unsigned long long pk2(float lo, float hi) {
    unsigned long long r;
    asm("mov.b64 %0, {%1, %2};" : "=l"(r) : "f"(lo), "f"(hi));
    return r;
}
__device__ __forceinline__ float2 up2(unsigned long long v) {
    float2 r;
    asm("mov.b64 {%0, %1}, %2;" : "=f"(r.x), "=f"(r.y) : "l"(v));
    return r;
}
__device__ __forceinline__ unsigned long long fma2(unsigned long long a,
                                                   unsigned long long b,
                                                   unsigned long long c) {
    unsigned long long r;
    asm("fma.rn.f32x2 %0, %1, %2, %3;" : "=l"(r) : "l"(a), "l"(b), "l"(c));
    return r;
}

// magic-number round-to-nearest-int for |x| < 2^22 (FADD+IADD, beats F2I)
__device__ __forceinline__ int magic_rni(float x) {
    return __float_as_int(x + MAGIC_F) - MAGIC_I;
}
// magic int->float for |s| < 2^22 (IADD+FADD, beats I2F)
__device__ __forceinline__ float magic_itf(int s) {
    return __int_as_float(s + MAGIC_I) - MAGIC_F;
}

// ---------------- kernel 1: combined mixture -> m, n, I ----------------
__global__ void setup_kernel(const float* __restrict__ means,
                             const float* __restrict__ L,
                             const float* __restrict__ mw,
                             const float* __restrict__ seeds) {
    __shared__ float Lc[DD][DD];
    __shared__ float mc[DD];
    int tid = threadIdx.x;

    float w0 = fmaxf(mw[0], 1e-6f);
    float w1 = fmaxf(mw[1], 1e-6f);
    float inv = 1.0f / (w0 + w1);
    w0 *= inv; w1 *= inv;

    if (tid < DD * DD) {
        int d = tid / DD, e = tid - d * DD;
        float a = L[d * DD + e];
        float c = L[DD * DD + d * DD + e];
        float v = 0.0f;
        if (e < d) {
            v = w0 * a + w1 * c;
        } else if (e == d) {
            v = w0 * (fabsf(a - 1e-12f) + 1e-12f)
              + w1 * (fabsf(c - 1e-12f) + 1e-12f);
        }
        Lc[d][e] = v;
    }
    if (tid < DD) mc[tid] = w0 * means[tid] + w1 * means[DD + tid];
    __syncthreads();

    int g = blockIdx.x * blockDim.x + tid;      // 0..2047 = s*512 + h
    int s = g >> 9, h = g & 511;

    float sd[DD];
    #pragma unroll
    for (int e = 0; e < DD; e++) sd[e] = seeds[(size_t)g * DD + e];

    float comb[DD];
    #pragma unroll
    for (int d = 0; d < DD; d++) {
        float v = mc[d];
        for (int e = 0; e <= d; e++) v = fmaf(Lc[d][e], sd[e], v);
        comb[d] = v;
    }
    g_m0[s][h] = comb[0];
    g_m1[s][h] = comb[1];
    g_n0[s][h] = comb[2];
    g_n1[s][h] = comb[3];
    #pragma unroll
    for (int i = 0; i < INPUT; i++) g_I[s][h][i] = comb[4 + i];
}

// ---------------- kernel 2: output channels 2..9 (x-only, via pinv@span == I) ----
__global__ __launch_bounds__(32) void xout_kernel(const float* __restrict__ x,
                                                  float* __restrict__ out) {
    const int b = blockIdx.x;
    const int lane = threadIdx.x;
    if (lane >= INPUT) return;

    const float* src = x + (size_t)b * SEQ * INPUT + lane;
    float* ob = out + (size_t)b * SEQ * OUTK + 2 + lane;

    float acc = 0.0f;
    #pragma unroll 8
    for (int t = 0; t < SEQ; t++) {
        acc = fmaf(0.9f, acc, ALPHA_F * src[(size_t)t * INPUT]);
        ob[(size_t)t * OUTK] = acc;
    }
}

// ---------------- kernel 3: the sequential RNN scan ----------------
// R10 skeleton + arc cuts: magic-number int<->float conversions (2^17 scale),
// decay+input fma2 hoisted pre-barrier, single STS.64 exchange slot per warp,
// out-scan FMAs computed by ALL threads (identical warp streams; STG on tid 96).
__global__ __launch_bounds__(128, 1) void rnn_kernel(const float* __restrict__ x,
                                                     const int* __restrict__ cur_seeds,
                                                     float* __restrict__ out) {
    const int b = blockIdx.x;
    const int tid = threadIdx.x;
    const int wid = tid >> 5, lane = tid & 31;
    const int s = cur_seeds[b];
    const int h0 = tid * 4;

    // n prescaled by 2^17 (scalar — q-dot consumes scalar tanh outputs)
    float4 N0 = *(const float4*)&g_n0[s][h0];
    float4 N1 = *(const float4*)&g_n1[s][h0];
    N0.x *= QSCALE; N0.y *= QSCALE; N0.z *= QSCALE; N0.w *= QSCALE;
    N1.x *= QSCALE; N1.y *= QSCALE; N1.z *= QSCALE; N1.w *= QSCALE;

    // m packed over unit pairs, K1*2^-17 folded in
    const float KQ = K1_F * QINV;
    float4 m0 = *(const float4*)&g_m0[s][h0];
    float4 m1 = *(const float4*)&g_m1[s][h0];
    const unsigned long long M0A = pk2(m0.x * KQ, m0.y * KQ);
    const unsigned long long M0B = pk2(m0.z * KQ, m0.w * KQ);
    const unsigned long long M1A = pk2(m1.x * KQ, m1.y * KQ);
    const unsigned long long M1B = pk2(m1.z * KQ, m1.w * KQ);

    // I packed over unit pairs, ALPHA folded in
    unsigned long long IwA[INPUT], IwB[INPUT];
    #pragma unroll
    for (int i = 0; i < INPUT; i++) {
        IwA[i] = pk2(ALPHA_F * g_I[s][h0 + 0][i], ALPHA_F * g_I[s][h0 + 1][i]);
        IwB[i] = pk2(ALPHA_F * g_I[s][h0 + 2][i], ALPHA_F * g_I[s][h0 + 3][i]);
    }

    const float* xb = x + (size_t)b * SEQ * INPUT;
    float2* ob01 = (float2*)(out + (size_t)b * SEQ * OUTK);   // channels 0,1
    const float K1S = K1_F * QINV;
    const unsigned long long C9 = pk2(0.9f, 0.9f);
    const unsigned long long ZU = 0ull;

    __shared__ __align__(16) unsigned long long isp[2][4];   // [parity][warp]: {iq0,iq1}

    unsigned long long hA = ZU, hB = ZU;          // packed (h0,h1),(h2,h3)
    float oa = 0.0f, obv = 0.0f;                  // out scans (all threads, identical)
    const bool outw = (tid == 96);                // warp 3 lane 0 stores

    float4 xA0 = *(const float4*)(xb + 0), xB0 = *(const float4*)(xb + 4);
    float4 xA1 = *(const float4*)(xb + 8), xB1 = *(const float4*)(xb + 12);

    #define RNN_STEP(PAR, T, XA, XB)                                              \
    {                                                                             \
        float2 hx = up2(hA), hy = up2(hB);                                        \
        float th0 = fast_tanh(hx.x);                                              \
        float th1 = fast_tanh(hx.y);                                              \
        float th2 = fast_tanh(hy.x);                                              \
        float th3 = fast_tanh(hy.y);                                              \
        float q0 = fmaf(N0.x, th0, N0.y * th1) + fmaf(N0.z, th2, N0.w * th3);     \
        float q1 = fmaf(N1.x, th0, N1.y * th1) + fmaf(N1.z, th2, N1.w * th3);     \
        int iq0 = magic_rni(q0);                                                  \
        int iq1 = magic_rni(q1);                                                  \
        iq0 = __reduce_add_sync(0xffffffffu, iq0);                                \
        iq1 = __reduce_add_sync(0xffffffffu, iq1);                                \
        if (lane == 0)                                                            \
            isp[PAR][wid] = ((unsigned long long)(unsigned)iq0 << 32)             \
                          | (unsigned)iq1;                                        \
        /* shadow work: aix + decay applied to h (p-independent) */               \
        unsigned long long xd0 = pk2(XA.x, XA.x), xd1 = pk2(XA.y, XA.y);          \
        unsigned long long xd2 = pk2(XA.z, XA.z), xd3 = pk2(XA.w, XA.w);          \
        unsigned long long xd4 = pk2(XB.x, XB.x), xd5 = pk2(XB.y, XB.y);          \
        unsigned long long xd6 = pk2(XB.z, XB.z), xd7 = pk2(XB.w, XB.w);          \
        unsigned long long aA = fma2(IwA[0], xd0, ZU);                            \
        unsigned long long aB = fma2(IwB[0], xd0, ZU);                            \
        aA = fma2(IwA[1], xd1, aA);  aB = fma2(IwB[1], xd1, aB);                  \
        aA = fma2(IwA[2], xd2, aA);  aB = fma2(IwB[2], xd2, aB);                  \
        aA = fma2(IwA[3], xd3, aA);  aB = fma2(IwB[3], xd3, aB);                  \
        aA = fma2(IwA[4], xd4, aA);  aB = fma2(IwB[4], xd4, aB);                  \
        aA = fma2(IwA[5], xd5, aA);  aB = fma2(IwB[5], xd5, aB);                  \
        aA = fma2(IwA[6], xd6, aA);  aB = fma2(IwB[6], xd6, aB);                  \
        aA = fma2(IwA[7], xd7, aA);  aB = fma2(IwB[7], xd7, aB);                  \
        hA = fma2(C9, hA, aA);   /* h' = 0.9h + aix, pre-barrier */               \
        hB = fma2(C9, hB, aB);                                                    \
        __syncthreads();                                                          \
        ulonglong2 w01 = *(const ulonglong2*)&isp[PAR][0];                        \
        ulonglong2 w23 = *(const ulonglong2*)&isp[PAR][2];                        \
        int s0 = (int)(unsigned)(w01.x >> 32) + (int)(unsigned)(w01.y >> 32)      \
               + (int)(unsigned)(w23.x >> 32) + (int)(unsigned)(w23.y >> 32);     \
        int s1 = (int)(unsigned)w01.x + (int)(unsigned)w01.y                      \
               + (int)(unsigned)w23.x + (int)(unsigned)w23.y;                     \
        float p0 = magic_itf(s0);                                                 \
        float p1 = magic_itf(s1);                                                 \
        unsigned long long p0d = pk2(p0, p0), p1d = pk2(p1, p1);                  \
        hA = fma2(M0A, p0d, fma2(M1A, p1d, hA));                                  \
        hB = fma2(M0B, p0d, fma2(M1B, p1d, hB));                                  \
        oa  = fmaf(0.9f, oa,  K1S * p0);   /* all threads: identical streams */   \
        obv = fmaf(0.9f, obv, K1S * p1);                                          \
        if (outw) ob01[(size_t)(T) * (OUTK / 2)] = make_float2(oa, obv);          \
    }

    for (int t = 0; t < SEQ; t += 2) {
        int tf = (t + 2 <= SEQ - 2) ? t + 2 : SEQ - 2;
        float4 nA0 = *(const float4*)(xb + (size_t)tf * INPUT);
        float4 nB0 = *(const float4*)(xb + (size_t)tf * INPUT + 4);
        float4 nA1 = *(const float4*)(xb + (size_t)(tf + 1) * INPUT);
        float4 nB1 = *(const float4*)(xb + (size_t)(tf + 1) * INPUT + 4);

        RNN_STEP(0, t,     xA0, xB0);
        RNN_STEP(1, t + 1, xA1, xB1);

        xA0 = nA0; xB0 = nB0; xA1 = nA1; xB1 = nB1;
    }
    #undef RNN_STEP
}

// ---------------- launch ----------------
extern "C" void kernel_launch(void* const* d_in, const int* in_sizes, int n_in,
                              void* d_out, int out_size) {
    const float* x     = (const float*)d_in[0];   // (64,2048,8)
    const float* means = (const float*)d_in[1];   // (2,12)
    const float* L     = (const float*)d_in[2];   // (2,12,12)
    const float* mw    = (const float*)d_in[3];   // (2,)
    const float* seeds = (const float*)d_in[4];   // (4,512,12)
    const int*   cs    = (const int*)d_in[5];     // (64,)
    float* out = (float*)d_out;                   // (64,2048,10)

    setup_kernel<<<8, 256>>>(means, L, mw, seeds);
    xout_kernel<<<BATCH, 32>>>(x, out);
    rnn_kernel<<<BATCH, 128>>>(x, cs, out);
}